// round 13
// baseline (speedup 1.0000x reference)
#include <cuda_runtime.h>
#include <cuda_fp16.h>
#include <cstdint>

// Problem constants
#define B_TOT 2048
#define T_LEN 128
#define DIN   64
#define UDIM  128
#define NG    512   // 4*U
#define KH    128   // recurrent K (h part only)
#define BT    16    // batch rows per phase-2 CTA
#define NTH2  128
#define XH_S  20    // h tile row stride (floats)
#define KUF   4

// ---------------- device globals ----------------
// phase-2 weights (permuted unit-major: col = u*4+gate), fp32
__device__ __align__(16) float g_Whh[KH * NG];
__device__ __align__(16) float g_bias[NG];            // permuted, b_ih+b_hh
// phase-1 weights: W_ih rows in PERMUTED order, fp16 split hi/lo, [perm_n][k]
__device__ __align__(16) __half g_Bhi[NG * DIN];
__device__ __align__(16) __half g_Blo[NG * DIN];
// phase-1 output: xw[path][b][t][512 perm cols] = x@Wih^T + bias  (1 GB scratch)
__device__ float g_xw[(size_t)2 * B_TOT * T_LEN * NG];

__global__ void prep_kernel(const float* __restrict__ W_ih, const float* __restrict__ W_hh,
                            const float* __restrict__ b_ih, const float* __restrict__ b_hh) {
    int k = blockIdx.x;                      // 0..191
    int n = threadIdx.x;                     // torch gate-major: gate = n>>7, unit = n&127
    int perm = (n & 127) * 4 + (n >> 7);     // unit-major permuted slot
    if (k < DIN) {
        float wv = W_ih[n * DIN + k];
        __half hi = __float2half_rn(wv);
        __half lo = __float2half_rn(wv - __half2float(hi));
        g_Bhi[perm * DIN + k] = hi;
        g_Blo[perm * DIN + k] = lo;
    } else {
        g_Whh[(k - DIN) * NG + perm] = W_hh[n * UDIM + (k - DIN)];
    }
    if (k == 0) g_bias[perm] = b_ih[n] + b_hh[n];
}

// ---------------- phase 1: xw = x @ W_ih^T + b  (fp16-split mma.sync) ----------------
__device__ __forceinline__ uint32_t h2hi(float2 v) {
    __half2 h = __floats2half2_rn(v.x, v.y);      // .x = low half
    return *(uint32_t*)&h;
}
__device__ __forceinline__ uint32_t h2lo(float2 v) {
    float rx = v.x - __half2float(__float2half_rn(v.x));
    float ry = v.y - __half2float(__float2half_rn(v.y));
    __half2 h = __floats2half2_rn(rx, ry);
    return *(uint32_t*)&h;
}

#define MMA16816(c0, c1, c2, c3, a0, a1, a2, a3, b0, b1)                      \
    asm volatile(                                                             \
        "mma.sync.aligned.m16n8k16.row.col.f32.f16.f16.f32 "                  \
        "{%0,%1,%2,%3}, {%4,%5,%6,%7}, {%8,%9}, {%0,%1,%2,%3};"               \
        : "+f"(c0), "+f"(c1), "+f"(c2), "+f"(c3)                              \
        : "r"(a0), "r"(a1), "r"(a2), "r"(a3), "r"(b0), "r"(b1))

// grid (2048, 2), 256 threads. Warp w covers t-rows 16w..16w+15 of one sample.
__global__ void __launch_bounds__(256)
phase1_kernel(const float* __restrict__ x_st, const float* __restrict__ x_sc) {
    const int b    = blockIdx.x;
    const int path = blockIdx.y;
    const float* __restrict__ xrow = (path ? x_sc : x_st) + (size_t)b * T_LEN * DIN;

    const int tid  = threadIdx.x;
    const int w    = tid >> 5;
    const int lane = tid & 31;
    const int g    = lane >> 2;      // group 0..7
    const int t4   = lane & 3;       // thread-in-group
    const int r0   = 16 * w + g;     // first t-row (second is r0+8)

    // A fragments: rows r0, r0+8; k = 0..63 as 4 k16-tiles; hi/lo fp16 splits.
    // m16n8k16 A map: a0=(r0, k0+2t,+1)  a1=(r0+8, same)  a2=(r0, k0+2t+8,+9)  a3=(r0+8, same)
    uint32_t Ah[4][4], Al[4][4];
#pragma unroll
    for (int j = 0; j < 4; j++) {
        int k0 = 16 * j;
        float2 v00 = *(const float2*)(xrow + (size_t)r0 * DIN + k0 + 2 * t4);
        float2 v10 = *(const float2*)(xrow + (size_t)(r0 + 8) * DIN + k0 + 2 * t4);
        float2 v01 = *(const float2*)(xrow + (size_t)r0 * DIN + k0 + 2 * t4 + 8);
        float2 v11 = *(const float2*)(xrow + (size_t)(r0 + 8) * DIN + k0 + 2 * t4 + 8);
        Ah[j][0] = h2hi(v00); Al[j][0] = h2lo(v00);
        Ah[j][1] = h2hi(v10); Al[j][1] = h2lo(v10);
        Ah[j][2] = h2hi(v01); Al[j][2] = h2lo(v01);
        Ah[j][3] = h2hi(v11); Al[j][3] = h2lo(v11);
    }

    float* __restrict__ obase = g_xw + ((size_t)(path * B_TOT + b)) * (T_LEN * NG);

    // B fragment map (col-major 16x8): b0=(k0+2t,+1, n0+g)  b1=(k0+2t+8,+9, n0+g)
    for (int nt = 0; nt < NG / 8; nt++) {
        const int n0 = nt * 8;
        const size_t brow = (size_t)(n0 + g) * DIN;
        float c0 = 0.f, c1 = 0.f, c2 = 0.f, c3 = 0.f;
#pragma unroll
        for (int j = 0; j < 4; j++) {
            int k0 = 16 * j;
            uint32_t bh0 = *(const uint32_t*)(g_Bhi + brow + k0 + 2 * t4);
            uint32_t bh1 = *(const uint32_t*)(g_Bhi + brow + k0 + 2 * t4 + 8);
            uint32_t bl0 = *(const uint32_t*)(g_Blo + brow + k0 + 2 * t4);
            uint32_t bl1 = *(const uint32_t*)(g_Blo + brow + k0 + 2 * t4 + 8);
            MMA16816(c0, c1, c2, c3, Ah[j][0], Ah[j][1], Ah[j][2], Ah[j][3], bh0, bh1);
            MMA16816(c0, c1, c2, c3, Al[j][0], Al[j][1], Al[j][2], Al[j][3], bh0, bh1);
            MMA16816(c0, c1, c2, c3, Ah[j][0], Ah[j][1], Ah[j][2], Ah[j][3], bl0, bl1);
        }
        // fold bias (cols n0+2t, n0+2t+1 for both rows)
        float2 bv = *(const float2*)(g_bias + n0 + 2 * t4);
        c0 += bv.x; c1 += bv.y; c2 += bv.x; c3 += bv.y;
        // D map: c0=(r0, n0+2t) c1=(r0, n0+2t+1) c2=(r0+8, n0+2t) c3=(r0+8, n0+2t+1)
        *(float2*)(obase + (size_t)r0 * NG + n0 + 2 * t4)       = make_float2(c0, c1);
        *(float2*)(obase + (size_t)(r0 + 8) * NG + n0 + 2 * t4) = make_float2(c2, c3);
    }
}

// ---------------- phase 2: fp32 recurrence, K=128 (h part only) ----------------
__device__ __forceinline__ float fsig(float x) { return 1.0f / (1.0f + __expf(-x)); }
__device__ __forceinline__ float ftanh(float x) {
    float a = fabsf(x);
    float e = __expf(2.0f * a);
    float r = 1.0f - 2.0f / (1.0f + e);
    return copysignf(r, x);
}
#define FFMA2(d, a, b) asm("fma.rn.f32x2 %0, %1, %2, %0;" : "+l"(d) : "l"(a), "l"(b))
__device__ __forceinline__ unsigned long long splat2(float w) {
    unsigned long long r; asm("mov.b64 %0, {%1, %1};" : "=l"(r) : "f"(w)); return r;
}
__device__ __forceinline__ unsigned long long pack2(float lo, float hi) {
    unsigned long long r; asm("mov.b64 %0, {%1, %2};" : "=l"(r) : "f"(lo), "f"(hi)); return r;
}
__device__ __forceinline__ void unpack2(unsigned long long p, float& lo, float& hi) {
    asm("mov.b64 {%0, %1}, %2;" : "=f"(lo), "=f"(hi) : "l"(p));
}
#define HBUF (UDIM * XH_S)   // 2560 floats per h buffer

__global__ void __launch_bounds__(NTH2, 2)
lstm_kernel(const float* __restrict__ bn_gamma, const float* __restrict__ bn_beta,
            const float* __restrict__ bn_mean, const float* __restrict__ bn_var,
            float* __restrict__ out) {
    __shared__ __align__(16) float sh[2 * HBUF];   // double-buffered h [u][b]

    const int path  = blockIdx.y;
    const int bbase = blockIdx.x * BT;
    const int i = threadIdx.x;   // unit u = i; owns gate cols {4i..4i+3}, all 16 rows

    for (int idx = i; idx < 2 * HBUF; idx += NTH2) sh[idx] = 0.0f;

    float c[16], m[16], s[16];
#pragma unroll
    for (int j = 0; j < 16; j++) { c[j] = 0.0f; m[j] = 0.0f; s[j] = 0.0f; }

    const float4* __restrict__ Wp = (const float4*)g_Whh;   // [k][128] float4
    float4 w[KUF], wn[KUF];
#pragma unroll
    for (int q = 0; q < KUF; q++) w[q] = __ldg(Wp + (size_t)q * (NG / 4) + i);

    // xw stream: thread i reads float4 {4i..4i+3} for rows bbase..bbase+15 at step t
    const float* __restrict__ xwb =
        g_xw + ((size_t)path * B_TOT + bbase) * (T_LEN * NG) + 4 * i;
    float4 xwr[16];
#pragma unroll
    for (int r = 0; r < 16; r++)
        xwr[r] = __ldg((const float4*)(xwb + (size_t)r * T_LEN * NG));

    for (int t = 0; t < T_LEN; t++) {
        const float* __restrict__ rd = sh + (t & 1) * HBUF;
        float* __restrict__ wr       = sh + ((t + 1) & 1) * HBUF;

        __syncthreads();   // h in rd visible; wr free

        // acc init = xw (bias already folded in phase 1)
        unsigned long long acc[4][8];
#pragma unroll
        for (int p = 0; p < 8; p++) {
            float4 lo = xwr[2 * p], hi = xwr[2 * p + 1];
            acc[0][p] = pack2(lo.x, hi.x);
            acc[1][p] = pack2(lo.y, hi.y);
            acc[2][p] = pack2(lo.z, hi.z);
            acc[3][p] = pack2(lo.w, hi.w);
        }

        // gemm over h: K = 128
#pragma unroll 2
        for (int kb = 0; kb < KH; kb += KUF) {
            int kn = (kb + KUF < KH) ? (kb + KUF) : 0;
#pragma unroll
            for (int q = 0; q < KUF; q++)
                wn[q] = __ldg(Wp + (size_t)(kn + q) * (NG / 4) + i);
#pragma unroll
            for (int q = 0; q < KUF; q++) {
                const ulonglong2* xr = (const ulonglong2*)(rd + (kb + q) * XH_S);
                ulonglong2 q0 = xr[0];
                ulonglong2 q1 = xr[1];
                ulonglong2 q2 = xr[2];
                ulonglong2 q3 = xr[3];
                const float* wf = (const float*)&w[q];
#pragma unroll
                for (int g = 0; g < 4; g++) {
                    unsigned long long wc = splat2(wf[g]);
                    FFMA2(acc[g][0], q0.x, wc);
                    FFMA2(acc[g][1], q0.y, wc);
                    FFMA2(acc[g][2], q1.x, wc);
                    FFMA2(acc[g][3], q1.y, wc);
                    FFMA2(acc[g][4], q2.x, wc);
                    FFMA2(acc[g][5], q2.y, wc);
                    FFMA2(acc[g][6], q3.x, wc);
                    FFMA2(acc[g][7], q3.y, wc);
                }
            }
#pragma unroll
            for (int q = 0; q < KUF; q++) w[q] = wn[q];
        }

        // prefetch next step's xw (consumed at next acc init)
        if (t + 1 < T_LEN) {
#pragma unroll
            for (int r = 0; r < 16; r++)
                xwr[r] = __ldg((const float4*)(xwb + ((size_t)r * T_LEN + (t + 1)) * NG));
        }

        // activations (gates in registers)
        float ig[16], fg[16], gg[16], og[16];
#pragma unroll
        for (int p = 0; p < 8; p++) {
            unpack2(acc[0][p], ig[2 * p], ig[2 * p + 1]);
            unpack2(acc[1][p], fg[2 * p], fg[2 * p + 1]);
            unpack2(acc[2][p], gg[2 * p], gg[2 * p + 1]);
            unpack2(acc[3][p], og[2 * p], og[2 * p + 1]);
        }
#pragma unroll
        for (int b = 0; b < 16; b++) {
            ig[b] = fsig(ig[b]);
            fg[b] = fsig(fg[b]);
            gg[b] = ftanh(gg[b]);
            og[b] = fsig(og[b]);
        }

        float hv[16];
        if (path) {        // ANN: h = o * tanh(c)
#pragma unroll
            for (int b = 0; b < 16; b++) {
                c[b] = fg[b] * c[b] + ig[b] * gg[b];
                hv[b] = og[b] * ftanh(c[b]);
                s[b] += hv[b];
            }
        } else {           // SNN integrate-and-fire, spikes feed back as h
#pragma unroll
            for (int b = 0; b < 16; b++) {
                c[b] = fg[b] * c[b] + ig[b] * gg[b];
                m[b] += og[b] * ftanh(c[b]);
                float spk = (m[b] >= 1.0f) ? 1.0f : 0.0f;
                m[b] -= spk;
                hv[b] = spk;
                s[b] += spk;
            }
        }
        {
            float4* hw = (float4*)(wr + (size_t)i * XH_S);
            hw[0] = make_float4(hv[0],  hv[1],  hv[2],  hv[3]);
            hw[1] = make_float4(hv[4],  hv[5],  hv[6],  hv[7]);
            hw[2] = make_float4(hv[8],  hv[9],  hv[10], hv[11]);
            hw[3] = make_float4(hv[12], hv[13], hv[14], hv[15]);
        }
    }

    // epilogue: temporal mean + BatchNorm
    float scale = bn_gamma[i] * rsqrtf(bn_var[i] + 1e-5f);
    float shift = bn_beta[i] - bn_mean[i] * scale;
    const float inv = 1.0f / (float)T_LEN;
#pragma unroll
    for (int b = 0; b < 16; b++) {
        out[((size_t)path * B_TOT + bbase + b) * UDIM + i] = s[b] * inv * scale + shift;
    }
}

extern "C" void kernel_launch(void* const* d_in, const int* in_sizes, int n_in,
                              void* d_out, int out_size) {
    const float* x_st  = (const float*)d_in[0];
    const float* x_sc  = (const float*)d_in[1];
    const float* W_ih  = (const float*)d_in[2];
    const float* W_hh  = (const float*)d_in[3];
    const float* b_ih  = (const float*)d_in[4];
    const float* b_hh  = (const float*)d_in[5];
    const float* gamma = (const float*)d_in[6];
    const float* beta  = (const float*)d_in[7];
    const float* mean  = (const float*)d_in[8];
    const float* var   = (const float*)d_in[9];

    prep_kernel<<<192, NG>>>(W_ih, W_hh, b_ih, b_hh);
    dim3 g1(B_TOT, 2);
    phase1_kernel<<<g1, 256>>>(x_st, x_sc);
    dim3 g2(B_TOT / BT, 2);
    lstm_kernel<<<g2, NTH2>>>(gamma, beta, mean, var, (float*)d_out);
}

// round 14
// speedup vs baseline: 1.2863x; 1.2863x over previous
#include <cuda_runtime.h>
#include <cuda_fp16.h>
#include <cstdint>

// Problem constants
#define B_TOT 2048
#define T_LEN 128
#define DIN   64
#define UDIM  128
#define NG    512   // 4*U
#define KH    128   // recurrent K (h part only)
#define BT    16    // batch rows per phase-2 CTA
#define NTH2  128
#define XH_S  20    // h tile row stride (floats)
#define KUF   4

// ---------------- device globals ----------------
// phase-2 weights (permuted unit-major: col = u*4+gate), fp32
__device__ __align__(16) float g_Whh[KH * NG];
__device__ __align__(16) float g_bias[NG];            // permuted, b_ih+b_hh
// phase-1 B operand, FRAGMENT-PACKED: [nt][j][lane] -> uint4 {bh0, bh1, bl0, bl1}
// nt = n-tile (8 cols), j = k-tile (16 k), lane = mma lane. One LDG.128 per fragment.
__device__ __align__(16) uint32_t g_Bpk[64 * 4 * 32 * 4];   // 128 KB
// phase-1 output: xw[path][b][t][512 perm cols] = x@Wih^T + bias  (1 GB scratch)
__device__ float g_xw[(size_t)2 * B_TOT * T_LEN * NG];

__global__ void prep_kernel(const float* __restrict__ W_ih, const float* __restrict__ W_hh,
                            const float* __restrict__ b_ih, const float* __restrict__ b_hh) {
    int k = blockIdx.x;                      // 0..191
    int n = threadIdx.x;                     // torch gate-major: gate = n>>7, unit = n&127
    int perm = (n & 127) * 4 + (n >> 7);     // unit-major permuted slot
    if (k >= DIN) {
        g_Whh[(k - DIN) * NG + perm] = W_hh[n * UDIM + (k - DIN)];
    }
    if (k == 0) g_bias[perm] = b_ih[n] + b_hh[n];
}

// pack W_ih into mma-fragment order, fp16 hi/lo split, directly from fp32 source
__device__ __forceinline__ uint32_t packh2(float a, float b) {
    __half2 h = __floats2half2_rn(a, b);     // .x = low half = first element
    return *(uint32_t*)&h;
}
__global__ void prep2_kernel(const float* __restrict__ W_ih) {
    const int nt   = blockIdx.x;             // 0..63
    const int j    = threadIdx.x >> 5;       // 0..3
    const int lane = threadIdx.x & 31;
    const int g    = lane >> 2;
    const int t4   = lane & 3;
    const int n_perm = nt * 8 + g;           // permuted column
    const int unit = n_perm >> 2, gate = n_perm & 3;
    const int tn   = gate * 128 + unit;      // original torch row of W_ih
    const float* __restrict__ row = W_ih + (size_t)tn * DIN;

    const int k0 = 16 * j + 2 * t4;
    float a0 = row[k0],     a1 = row[k0 + 1];
    float b0 = row[k0 + 8], b1 = row[k0 + 9];
    float h_a0 = __half2float(__float2half_rn(a0));
    float h_a1 = __half2float(__float2half_rn(a1));
    float h_b0 = __half2float(__float2half_rn(b0));
    float h_b1 = __half2float(__float2half_rn(b1));

    uint4 v;
    v.x = packh2(a0, a1);                    // bh0
    v.y = packh2(b0, b1);                    // bh1
    v.z = packh2(a0 - h_a0, a1 - h_a1);      // bl0
    v.w = packh2(b0 - h_b0, b1 - h_b1);      // bl1
    ((uint4*)g_Bpk)[(nt * 4 + j) * 32 + lane] = v;
}

// ---------------- phase 1: xw = x @ W_ih^T + b  (fp16-split mma.sync) ----------------
__device__ __forceinline__ uint32_t h2hi(float2 v) {
    __half2 h = __floats2half2_rn(v.x, v.y);
    return *(uint32_t*)&h;
}
__device__ __forceinline__ uint32_t h2lo(float2 v) {
    float rx = v.x - __half2float(__float2half_rn(v.x));
    float ry = v.y - __half2float(__float2half_rn(v.y));
    __half2 h = __floats2half2_rn(rx, ry);
    return *(uint32_t*)&h;
}

#define MMA16816(c0, c1, c2, c3, a0, a1, a2, a3, b0, b1)                      \
    asm volatile(                                                             \
        "mma.sync.aligned.m16n8k16.row.col.f32.f16.f16.f32 "                  \
        "{%0,%1,%2,%3}, {%4,%5,%6,%7}, {%8,%9}, {%0,%1,%2,%3};"               \
        : "+f"(c0), "+f"(c1), "+f"(c2), "+f"(c3)                              \
        : "r"(a0), "r"(a1), "r"(a2), "r"(a3), "r"(b0), "r"(b1))

// grid (2048, 2), 256 threads. Warp w covers t-rows 16w..16w+15 of one sample.
__global__ void __launch_bounds__(256)
phase1_kernel(const float* __restrict__ x_st, const float* __restrict__ x_sc) {
    const int b    = blockIdx.x;
    const int path = blockIdx.y;
    const float* __restrict__ xrow = (path ? x_sc : x_st) + (size_t)b * T_LEN * DIN;

    const int tid  = threadIdx.x;
    const int w    = tid >> 5;
    const int lane = tid & 31;
    const int g    = lane >> 2;      // group 0..7
    const int t4   = lane & 3;       // thread-in-group
    const int r0   = 16 * w + g;     // first t-row (second is r0+8)

    // A fragments: rows r0, r0+8; k = 0..63 as 4 k16-tiles; hi/lo fp16 splits.
    uint32_t Ah[4][4], Al[4][4];
#pragma unroll
    for (int j = 0; j < 4; j++) {
        int k0 = 16 * j;
        float2 v00 = *(const float2*)(xrow + (size_t)r0 * DIN + k0 + 2 * t4);
        float2 v10 = *(const float2*)(xrow + (size_t)(r0 + 8) * DIN + k0 + 2 * t4);
        float2 v01 = *(const float2*)(xrow + (size_t)r0 * DIN + k0 + 2 * t4 + 8);
        float2 v11 = *(const float2*)(xrow + (size_t)(r0 + 8) * DIN + k0 + 2 * t4 + 8);
        Ah[j][0] = h2hi(v00); Al[j][0] = h2lo(v00);
        Ah[j][1] = h2hi(v10); Al[j][1] = h2lo(v10);
        Ah[j][2] = h2hi(v01); Al[j][2] = h2lo(v01);
        Ah[j][3] = h2hi(v11); Al[j][3] = h2lo(v11);
    }

    float* __restrict__ obase = g_xw + ((size_t)(path * B_TOT + b)) * (T_LEN * NG);
    const uint4* __restrict__ bp = (const uint4*)g_Bpk;

    for (int nt = 0; nt < NG / 8; nt++) {
        const int n0 = nt * 8;
        // one coalesced LDG.128 per k-tile: this lane's 4 B words
        uint4 bf[4];
#pragma unroll
        for (int j = 0; j < 4; j++) bf[j] = __ldg(bp + (nt * 4 + j) * 32 + lane);

        float c0 = 0.f, c1 = 0.f, c2 = 0.f, c3 = 0.f;
#pragma unroll
        for (int j = 0; j < 4; j++) {
            MMA16816(c0, c1, c2, c3, Ah[j][0], Ah[j][1], Ah[j][2], Ah[j][3], bf[j].x, bf[j].y);
            MMA16816(c0, c1, c2, c3, Al[j][0], Al[j][1], Al[j][2], Al[j][3], bf[j].x, bf[j].y);
            MMA16816(c0, c1, c2, c3, Ah[j][0], Ah[j][1], Ah[j][2], Ah[j][3], bf[j].z, bf[j].w);
        }
        // fold bias (cols n0+2t4, n0+2t4+1 for both rows)
        float2 bv = *(const float2*)(g_bias + n0 + 2 * t4);
        c0 += bv.x; c1 += bv.y; c2 += bv.x; c3 += bv.y;
        *(float2*)(obase + (size_t)r0 * NG + n0 + 2 * t4)       = make_float2(c0, c1);
        *(float2*)(obase + (size_t)(r0 + 8) * NG + n0 + 2 * t4) = make_float2(c2, c3);
    }
}

// ---------------- phase 2: fp32 recurrence, K=128 (h part only) ----------------
__device__ __forceinline__ float fsig(float x) { return 1.0f / (1.0f + __expf(-x)); }
__device__ __forceinline__ float ftanh(float x) {
    float a = fabsf(x);
    float e = __expf(2.0f * a);
    float r = 1.0f - 2.0f / (1.0f + e);
    return copysignf(r, x);
}
#define FFMA2(d, a, b) asm("fma.rn.f32x2 %0, %1, %2, %0;" : "+l"(d) : "l"(a), "l"(b))
__device__ __forceinline__ unsigned long long splat2(float w) {
    unsigned long long r; asm("mov.b64 %0, {%1, %1};" : "=l"(r) : "f"(w)); return r;
}
__device__ __forceinline__ unsigned long long pack2(float lo, float hi) {
    unsigned long long r; asm("mov.b64 %0, {%1, %2};" : "=l"(r) : "f"(lo), "f"(hi)); return r;
}
__device__ __forceinline__ void unpack2(unsigned long long p, float& lo, float& hi) {
    asm("mov.b64 {%0, %1}, %2;" : "=f"(lo), "=f"(hi) : "l"(p));
}
#define HBUF (UDIM * XH_S)   // 2560 floats per h buffer

__global__ void __launch_bounds__(NTH2, 2)
lstm_kernel(const float* __restrict__ bn_gamma, const float* __restrict__ bn_beta,
            const float* __restrict__ bn_mean, const float* __restrict__ bn_var,
            float* __restrict__ out) {
    __shared__ __align__(16) float sh[2 * HBUF];   // double-buffered h [u][b]

    const int path  = blockIdx.y;
    const int bbase = blockIdx.x * BT;
    const int i = threadIdx.x;   // unit u = i; owns gate cols {4i..4i+3}, all 16 rows

    for (int idx = i; idx < 2 * HBUF; idx += NTH2) sh[idx] = 0.0f;

    float c[16], m[16], s[16];
#pragma unroll
    for (int j = 0; j < 16; j++) { c[j] = 0.0f; m[j] = 0.0f; s[j] = 0.0f; }

    const float4* __restrict__ Wp = (const float4*)g_Whh;   // [k][128] float4
    float4 w[KUF], wn[KUF];
#pragma unroll
    for (int q = 0; q < KUF; q++) w[q] = __ldg(Wp + (size_t)q * (NG / 4) + i);

    // xw stream: thread i reads float4 {4i..4i+3} for rows bbase..bbase+15 at step t
    const float* __restrict__ xwb =
        g_xw + ((size_t)path * B_TOT + bbase) * (T_LEN * NG) + 4 * i;
    float4 xwr[16];
#pragma unroll
    for (int r = 0; r < 16; r++)
        xwr[r] = __ldg((const float4*)(xwb + (size_t)r * T_LEN * NG));

    for (int t = 0; t < T_LEN; t++) {
        const float* __restrict__ rd = sh + (t & 1) * HBUF;
        float* __restrict__ wr       = sh + ((t + 1) & 1) * HBUF;

        __syncthreads();   // h in rd visible; wr free

        // acc init = xw (bias already folded in phase 1)
        unsigned long long acc[4][8];
#pragma unroll
        for (int p = 0; p < 8; p++) {
            float4 lo = xwr[2 * p], hi = xwr[2 * p + 1];
            acc[0][p] = pack2(lo.x, hi.x);
            acc[1][p] = pack2(lo.y, hi.y);
            acc[2][p] = pack2(lo.z, hi.z);
            acc[3][p] = pack2(lo.w, hi.w);
        }

        // gemm over h: K = 128
#pragma unroll 2
        for (int kb = 0; kb < KH; kb += KUF) {
            int kn = (kb + KUF < KH) ? (kb + KUF) : 0;
#pragma unroll
            for (int q = 0; q < KUF; q++)
                wn[q] = __ldg(Wp + (size_t)(kn + q) * (NG / 4) + i);
#pragma unroll
            for (int q = 0; q < KUF; q++) {
                const ulonglong2* xr = (const ulonglong2*)(rd + (kb + q) * XH_S);
                ulonglong2 q0 = xr[0];
                ulonglong2 q1 = xr[1];
                ulonglong2 q2 = xr[2];
                ulonglong2 q3 = xr[3];
                const float* wf = (const float*)&w[q];
#pragma unroll
                for (int g = 0; g < 4; g++) {
                    unsigned long long wc = splat2(wf[g]);
                    FFMA2(acc[g][0], q0.x, wc);
                    FFMA2(acc[g][1], q0.y, wc);
                    FFMA2(acc[g][2], q1.x, wc);
                    FFMA2(acc[g][3], q1.y, wc);
                    FFMA2(acc[g][4], q2.x, wc);
                    FFMA2(acc[g][5], q2.y, wc);
                    FFMA2(acc[g][6], q3.x, wc);
                    FFMA2(acc[g][7], q3.y, wc);
                }
            }
#pragma unroll
            for (int q = 0; q < KUF; q++) w[q] = wn[q];
        }

        // prefetch next step's xw (consumed at next acc init)
        if (t + 1 < T_LEN) {
#pragma unroll
            for (int r = 0; r < 16; r++)
                xwr[r] = __ldg((const float4*)(xwb + ((size_t)r * T_LEN + (t + 1)) * NG));
        }

        // activations (gates in registers)
        float ig[16], fg[16], gg[16], og[16];
#pragma unroll
        for (int p = 0; p < 8; p++) {
            unpack2(acc[0][p], ig[2 * p], ig[2 * p + 1]);
            unpack2(acc[1][p], fg[2 * p], fg[2 * p + 1]);
            unpack2(acc[2][p], gg[2 * p], gg[2 * p + 1]);
            unpack2(acc[3][p], og[2 * p], og[2 * p + 1]);
        }
#pragma unroll
        for (int b = 0; b < 16; b++) {
            ig[b] = fsig(ig[b]);
            fg[b] = fsig(fg[b]);
            gg[b] = ftanh(gg[b]);
            og[b] = fsig(og[b]);
        }

        float hv[16];
        if (path) {        // ANN: h = o * tanh(c)
#pragma unroll
            for (int b = 0; b < 16; b++) {
                c[b] = fg[b] * c[b] + ig[b] * gg[b];
                hv[b] = og[b] * ftanh(c[b]);
                s[b] += hv[b];
            }
        } else {           // SNN integrate-and-fire, spikes feed back as h
#pragma unroll
            for (int b = 0; b < 16; b++) {
                c[b] = fg[b] * c[b] + ig[b] * gg[b];
                m[b] += og[b] * ftanh(c[b]);
                float spk = (m[b] >= 1.0f) ? 1.0f : 0.0f;
                m[b] -= spk;
                hv[b] = spk;
                s[b] += spk;
            }
        }
        {
            float4* hw = (float4*)(wr + (size_t)i * XH_S);
            hw[0] = make_float4(hv[0],  hv[1],  hv[2],  hv[3]);
            hw[1] = make_float4(hv[4],  hv[5],  hv[6],  hv[7]);
            hw[2] = make_float4(hv[8],  hv[9],  hv[10], hv[11]);
            hw[3] = make_float4(hv[12], hv[13], hv[14], hv[15]);
        }
    }

    // epilogue: temporal mean + BatchNorm
    float scale = bn_gamma[i] * rsqrtf(bn_var[i] + 1e-5f);
    float shift = bn_beta[i] - bn_mean[i] * scale;
    const float inv = 1.0f / (float)T_LEN;
#pragma unroll
    for (int b = 0; b < 16; b++) {
        out[((size_t)path * B_TOT + bbase + b) * UDIM + i] = s[b] * inv * scale + shift;
    }
}

extern "C" void kernel_launch(void* const* d_in, const int* in_sizes, int n_in,
                              void* d_out, int out_size) {
    const float* x_st  = (const float*)d_in[0];
    const float* x_sc  = (const float*)d_in[1];
    const float* W_ih  = (const float*)d_in[2];
    const float* W_hh  = (const float*)d_in[3];
    const float* b_ih  = (const float*)d_in[4];
    const float* b_hh  = (const float*)d_in[5];
    const float* gamma = (const float*)d_in[6];
    const float* beta  = (const float*)d_in[7];
    const float* mean  = (const float*)d_in[8];
    const float* var   = (const float*)d_in[9];

    prep_kernel<<<192, NG>>>(W_ih, W_hh, b_ih, b_hh);
    prep2_kernel<<<64, 128>>>(W_ih);
    dim3 g1(B_TOT, 2);
    phase1_kernel<<<g1, 256>>>(x_st, x_sc);
    dim3 g2(B_TOT / BT, 2);
    lstm_kernel<<<g2, NTH2>>>(gamma, beta, mean, var, (float*)d_out);
}

// round 15
// speedup vs baseline: 1.6131x; 1.2541x over previous
#include <cuda_runtime.h>
#include <cuda_fp16.h>
#include <cstdint>

// Problem constants
#define B_TOT 2048
#define T_LEN 128
#define DIN   64
#define UDIM  128
#define NG    512   // 4*U
#define BT    16    // batch rows per phase-2 CTA
#define ST    136   // h smem row stride in halves (272 B: odd*16B, ldmatrix conflict-free)

// ---------------- device globals ----------------
__device__ __align__(16) float g_bias[NG];            // permuted, b_ih+b_hh (phase-1 fold)
// phase-1 B operand (W_ih), fragment-packed: [nt][kt(4)][lane] uint4 {bh0,bh1,bl0,bl1}
__device__ __align__(16) uint32_t g_Bpk[64 * 4 * 32 * 4];   // 128 KB
// phase-2 B operand (W_hh), fragment-packed: [kt(8)][nt(64)][lane] uint4 {bh0,bh1,bl0,bl1}
__device__ __align__(16) uint32_t g_Wpk[8 * 64 * 32 * 4];   // 256 KB
// phase-1 output: xw[path][b][t][512 perm cols] = x@Wih^T + bias  (1 GB scratch)
__device__ float g_xw[(size_t)2 * B_TOT * T_LEN * NG];

__device__ __forceinline__ uint32_t packh2(float a, float b) {
    __half2 h = __floats2half2_rn(a, b);     // .x = low half = first element
    return *(uint32_t*)&h;
}

// bias (permuted) for phase-1 fold
__global__ void prep_kernel(const float* __restrict__ b_ih, const float* __restrict__ b_hh) {
    int n = threadIdx.x;                     // torch gate-major: gate = n>>7, unit = n&127
    int perm = (n & 127) * 4 + (n >> 7);
    g_bias[perm] = b_ih[n] + b_hh[n];
}

// pack W_ih into phase-1 mma-fragment order, fp16 hi/lo
__global__ void prep2_kernel(const float* __restrict__ W_ih) {
    const int nt   = blockIdx.x;             // 0..63
    const int j    = threadIdx.x >> 5;       // k-tile 0..3
    const int lane = threadIdx.x & 31;
    const int g    = lane >> 2;
    const int t4   = lane & 3;
    const int n_perm = nt * 8 + g;
    const int unit = n_perm >> 2, gate = n_perm & 3;
    const int tn   = gate * 128 + unit;      // torch row of W_ih
    const float* __restrict__ row = W_ih + (size_t)tn * DIN;
    const int k0 = 16 * j + 2 * t4;
    float a0 = row[k0], a1 = row[k0 + 1], b0 = row[k0 + 8], b1 = row[k0 + 9];
    float ha0 = __half2float(__float2half_rn(a0));
    float ha1 = __half2float(__float2half_rn(a1));
    float hb0 = __half2float(__float2half_rn(b0));
    float hb1 = __half2float(__float2half_rn(b1));
    uint4 v;
    v.x = packh2(a0, a1);
    v.y = packh2(b0, b1);
    v.z = packh2(a0 - ha0, a1 - ha1);
    v.w = packh2(b0 - hb0, b1 - hb1);
    ((uint4*)g_Bpk)[(nt * 4 + j) * 32 + lane] = v;
}

// pack W_hh into phase-2 mma-fragment order, fp16 hi/lo: index [kt][nt][lane]
__global__ void prep3_kernel(const float* __restrict__ W_hh) {
    const int nt   = blockIdx.x;             // 0..63
    const int kt   = threadIdx.x >> 5;       // 0..7
    const int lane = threadIdx.x & 31;
    const int g    = lane >> 2;
    const int t4   = lane & 3;
    const int n_perm = nt * 8 + g;
    const int unit = n_perm >> 2, gate = n_perm & 3;
    const int tn   = gate * 128 + unit;      // torch row of W_hh
    const float* __restrict__ row = W_hh + (size_t)tn * UDIM;
    const int k0 = 16 * kt + 2 * t4;
    float a0 = row[k0], a1 = row[k0 + 1], b0 = row[k0 + 8], b1 = row[k0 + 9];
    float ha0 = __half2float(__float2half_rn(a0));
    float ha1 = __half2float(__float2half_rn(a1));
    float hb0 = __half2float(__float2half_rn(b0));
    float hb1 = __half2float(__float2half_rn(b1));
    uint4 v;
    v.x = packh2(a0, a1);
    v.y = packh2(b0, b1);
    v.z = packh2(a0 - ha0, a1 - ha1);
    v.w = packh2(b0 - hb0, b1 - hb1);
    ((uint4*)g_Wpk)[(kt * 64 + nt) * 32 + lane] = v;
}

// ---------------- shared mma helpers ----------------
#define MMA16816(c0, c1, c2, c3, a0, a1, a2, a3, b0, b1)                      \
    asm volatile(                                                             \
        "mma.sync.aligned.m16n8k16.row.col.f32.f16.f16.f32 "                  \
        "{%0,%1,%2,%3}, {%4,%5,%6,%7}, {%8,%9}, {%0,%1,%2,%3};"               \
        : "+f"(c0), "+f"(c1), "+f"(c2), "+f"(c3)                              \
        : "r"(a0), "r"(a1), "r"(a2), "r"(a3), "r"(b0), "r"(b1))

#define LDSM_X4(r0, r1, r2, r3, addr)                                         \
    asm volatile("ldmatrix.sync.aligned.m8n8.x4.shared.b16 {%0,%1,%2,%3}, [%4];" \
        : "=r"(r0), "=r"(r1), "=r"(r2), "=r"(r3) : "r"(addr))

__device__ __forceinline__ uint32_t h2hi(float2 v) {
    __half2 h = __floats2half2_rn(v.x, v.y);
    return *(uint32_t*)&h;
}
__device__ __forceinline__ uint32_t h2lo(float2 v) {
    float rx = v.x - __half2float(__float2half_rn(v.x));
    float ry = v.y - __half2float(__float2half_rn(v.y));
    __half2 h = __floats2half2_rn(rx, ry);
    return *(uint32_t*)&h;
}

// ---------------- phase 1: xw = x @ W_ih^T + b  (unchanged from R14, passing) ----------------
__global__ void __launch_bounds__(256)
phase1_kernel(const float* __restrict__ x_st, const float* __restrict__ x_sc) {
    const int b    = blockIdx.x;
    const int path = blockIdx.y;
    const float* __restrict__ xrow = (path ? x_sc : x_st) + (size_t)b * T_LEN * DIN;

    const int tid  = threadIdx.x;
    const int w    = tid >> 5;
    const int lane = tid & 31;
    const int g    = lane >> 2;
    const int t4   = lane & 3;
    const int r0   = 16 * w + g;

    uint32_t Ah[4][4], Al[4][4];
#pragma unroll
    for (int j = 0; j < 4; j++) {
        int k0 = 16 * j;
        float2 v00 = *(const float2*)(xrow + (size_t)r0 * DIN + k0 + 2 * t4);
        float2 v10 = *(const float2*)(xrow + (size_t)(r0 + 8) * DIN + k0 + 2 * t4);
        float2 v01 = *(const float2*)(xrow + (size_t)r0 * DIN + k0 + 2 * t4 + 8);
        float2 v11 = *(const float2*)(xrow + (size_t)(r0 + 8) * DIN + k0 + 2 * t4 + 8);
        Ah[j][0] = h2hi(v00); Al[j][0] = h2lo(v00);
        Ah[j][1] = h2hi(v10); Al[j][1] = h2lo(v10);
        Ah[j][2] = h2hi(v01); Al[j][2] = h2lo(v01);
        Ah[j][3] = h2hi(v11); Al[j][3] = h2lo(v11);
    }

    float* __restrict__ obase = g_xw + ((size_t)(path * B_TOT + b)) * (T_LEN * NG);
    const uint4* __restrict__ bp = (const uint4*)g_Bpk;

    for (int nt = 0; nt < NG / 8; nt++) {
        const int n0 = nt * 8;
        uint4 bf[4];
#pragma unroll
        for (int j = 0; j < 4; j++) bf[j] = __ldg(bp + (nt * 4 + j) * 32 + lane);

        float c0 = 0.f, c1 = 0.f, c2 = 0.f, c3 = 0.f;
#pragma unroll
        for (int j = 0; j < 4; j++) {
            MMA16816(c0, c1, c2, c3, Ah[j][0], Ah[j][1], Ah[j][2], Ah[j][3], bf[j].x, bf[j].y);
            MMA16816(c0, c1, c2, c3, Al[j][0], Al[j][1], Al[j][2], Al[j][3], bf[j].x, bf[j].y);
            MMA16816(c0, c1, c2, c3, Ah[j][0], Ah[j][1], Ah[j][2], Ah[j][3], bf[j].z, bf[j].w);
        }
        float2 bv = *(const float2*)(g_bias + n0 + 2 * t4);
        c0 += bv.x; c1 += bv.y; c2 += bv.x; c3 += bv.y;
        *(float2*)(obase + (size_t)r0 * NG + n0 + 2 * t4)       = make_float2(c0, c1);
        *(float2*)(obase + (size_t)(r0 + 8) * NG + n0 + 2 * t4) = make_float2(c2, c3);
    }
}

// ---------------- phase 2: tensor-core recurrence ----------------
__device__ __forceinline__ float fsig(float x) { return 1.0f / (1.0f + __expf(-x)); }
__device__ __forceinline__ float ftanh(float x) {
    float a = fabsf(x);
    float e = __expf(2.0f * a);
    float r = 1.0f - 2.0f / (1.0f + e);
    return copysignf(r, x);
}

// grid (128, 2), 128 threads (4 warps). Warp w owns permuted cols w*128..w*128+127
// (= units w*32..w*32+31, all 4 gates). Lane (g,t4): after shfl assembly, owns
// unit u = w*32 + 2*ln + (t4>>1), row = g + 8*(t4&1), for ln = 0..15.
__global__ void __launch_bounds__(128, 2)
lstm_tc_kernel(const float* __restrict__ bn_gamma, const float* __restrict__ bn_beta,
               const float* __restrict__ bn_mean, const float* __restrict__ bn_var,
               float* __restrict__ out) {
    // h buffers: [parity][hi=0/lo=1][16 rows x ST halves]; SNN uses hi only.
    __shared__ __align__(16) __half hbuf[2][2][16 * ST];   // 17408 B

    const int path  = blockIdx.y;            // 0 = SNN, 1 = ANN
    const int bbase = blockIdx.x * BT;
    const int tid   = threadIdx.x;
    const int w     = tid >> 5;
    const int lane  = tid & 31;
    const int g     = lane >> 2;
    const int t4    = lane & 3;
    const int row   = g + 8 * (t4 & 1);      // this lane's batch row (after assembly)
    const int du    = t4 >> 1;               // unit offset within n-tile pair

    // zero both h buffers (h0 = 0)
    for (int idx = tid; idx < 2 * 2 * 16 * ST / 2; idx += 128)
        ((uint32_t*)hbuf)[idx] = 0;

    float c[16], m[16], s[16];
#pragma unroll
    for (int j = 0; j < 16; j++) { c[j] = 0.0f; m[j] = 0.0f; s[j] = 0.0f; }

    // xw stream in state layout: float4 = 4 gates of unit u at (row, t)
    const float* __restrict__ xwbase =
        g_xw + (size_t)(path * B_TOT + bbase + row) * (T_LEN * NG) + (w * 32 + du) * 4;
    float4 xwr[16];
#pragma unroll
    for (int ln = 0; ln < 16; ln++)
        xwr[ln] = __ldg((const float4*)(xwbase + ln * 8));

    // ldmatrix per-lane address offset (row, col-half within tile)
    const int lrow = lane & 15;
    const int lcol = (lane >> 4) * 8;
    const uint32_t lmoff = (uint32_t)(lrow * ST + lcol) * 2;
    const uint32_t hi0 = (uint32_t)__cvta_generic_to_shared(&hbuf[0][0][0]);
    const uint32_t lo0 = (uint32_t)__cvta_generic_to_shared(&hbuf[0][1][0]);
    const uint32_t hi1 = (uint32_t)__cvta_generic_to_shared(&hbuf[1][0][0]);
    const uint32_t lo1 = (uint32_t)__cvta_generic_to_shared(&hbuf[1][1][0]);

    const uint4* __restrict__ wp = (const uint4*)g_Wpk;

    for (int t = 0; t < T_LEN; t++) {
        const int rp = t & 1;
        const uint32_t ah_base = (rp ? hi1 : hi0) + lmoff;
        const uint32_t al_base = (rp ? lo1 : lo0) + lmoff;
        __half* __restrict__ whi = &hbuf[rp ^ 1][0][0];
        __half* __restrict__ wlo = &hbuf[rp ^ 1][1][0];

        __syncthreads();   // h(t) visible; write-buffer free

        float acc[16][4];
#pragma unroll
        for (int ln = 0; ln < 16; ln++) {
            acc[ln][0] = 0.f; acc[ln][1] = 0.f; acc[ln][2] = 0.f; acc[ln][3] = 0.f;
        }

#pragma unroll 2
        for (int kt = 0; kt < 8; kt++) {
            uint32_t a0, a1, a2, a3;
            LDSM_X4(a0, a1, a2, a3, ah_base + kt * 32);
            uint32_t l0 = 0, l1 = 0, l2 = 0, l3 = 0;
            if (path) { LDSM_X4(l0, l1, l2, l3, al_base + kt * 32); }
#pragma unroll
            for (int ln = 0; ln < 16; ln++) {
                uint4 bf = __ldg(wp + (kt * 64 + w * 16 + ln) * 32 + lane);
                MMA16816(acc[ln][0], acc[ln][1], acc[ln][2], acc[ln][3],
                         a0, a1, a2, a3, bf.x, bf.y);
                if (path) {
                    MMA16816(acc[ln][0], acc[ln][1], acc[ln][2], acc[ln][3],
                             l0, l1, l2, l3, bf.x, bf.y);
                }
                MMA16816(acc[ln][0], acc[ln][1], acc[ln][2], acc[ln][3],
                         a0, a1, a2, a3, bf.z, bf.w);
            }
        }

        // assemble gates per (unit,row), add xw, activate, update state, store h
#pragma unroll
        for (int ln = 0; ln < 16; ln++) {
            float c0 = acc[ln][0], c1 = acc[ln][1], c2 = acc[ln][2], c3 = acc[ln][3];
            float s0 = (t4 & 1) ? c0 : c2;
            float s1 = (t4 & 1) ? c1 : c3;
            float r0 = __shfl_xor_sync(0xFFFFFFFFu, s0, 1);
            float r1 = __shfl_xor_sync(0xFFFFFFFFu, s1, 1);
            float pi, pf, pg, po;
            if (t4 & 1) { pi = r0; pf = r1; pg = c2; po = c3; }
            else        { pi = c0; pf = c1; pg = r0; po = r1; }
            float4 xw = xwr[ln];
            pi = fsig(pi + xw.x);
            pf = fsig(pf + xw.y);
            pg = ftanh(pg + xw.z);
            po = fsig(po + xw.w);
            c[ln] = pf * c[ln] + pi * pg;
            float h;
            if (path) {                       // ANN
                h = po * ftanh(c[ln]);
                s[ln] += h;
            } else {                          // SNN integrate-and-fire
                m[ln] += po * ftanh(c[ln]);
                h = (m[ln] >= 1.0f) ? 1.0f : 0.0f;
                m[ln] -= h;
                s[ln] += h;
            }
            int uoff = row * ST + w * 32 + 2 * ln + du;
            __half hh = __float2half_rn(h);
            whi[uoff] = hh;
            if (path) wlo[uoff] = __float2half_rn(h - __half2float(hh));
        }

        // prefetch next step's xw (hidden under next gemm)
        if (t + 1 < T_LEN) {
#pragma unroll
            for (int ln = 0; ln < 16; ln++)
                xwr[ln] = __ldg((const float4*)(xwbase + (size_t)(t + 1) * NG + ln * 8));
        }
    }

    // epilogue: temporal mean + BatchNorm (eval)
    const float inv = 1.0f / (float)T_LEN;
#pragma unroll
    for (int ln = 0; ln < 16; ln++) {
        int u = w * 32 + 2 * ln + du;
        float scale = __ldg(bn_gamma + u) * rsqrtf(__ldg(bn_var + u) + 1e-5f);
        float shift = __ldg(bn_beta + u) - __ldg(bn_mean + u) * scale;
        out[(size_t)(path * B_TOT + bbase + row) * UDIM + u] = s[ln] * inv * scale + shift;
    }
}

extern "C" void kernel_launch(void* const* d_in, const int* in_sizes, int n_in,
                              void* d_out, int out_size) {
    const float* x_st  = (const float*)d_in[0];
    const float* x_sc  = (const float*)d_in[1];
    const float* W_ih  = (const float*)d_in[2];
    const float* W_hh  = (const float*)d_in[3];
    const float* b_ih  = (const float*)d_in[4];
    const float* b_hh  = (const float*)d_in[5];
    const float* gamma = (const float*)d_in[6];
    const float* beta  = (const float*)d_in[7];
    const float* mean  = (const float*)d_in[8];
    const float* var   = (const float*)d_in[9];

    prep_kernel<<<1, NG>>>(b_ih, b_hh);
    prep2_kernel<<<64, 128>>>(W_ih);
    prep3_kernel<<<64, 256>>>(W_hh);
    dim3 g1(B_TOT, 2);
    phase1_kernel<<<g1, 256>>>(x_st, x_sc);
    dim3 g2(B_TOT / BT, 2);
    lstm_tc_kernel<<<g2, 128>>>(gamma, beta, mean, var, (float*)d_out);
}